// round 14
// baseline (speedup 1.0000x reference)
#include <cuda_runtime.h>
#include <math.h>
#include <stdint.h>

// ---------------- problem constants ----------------
#define N_NODES 10000
#define E_EDGES 320000
#define E_TOT   (E_EDGES + N_NODES)   // with self-loops
#define FIN     256
#define HD      128                   // channels per head
#define HH      4                     // heads (layers 1,2)
#define F1      (HH * HD)             // 512
#define M_PAD   10112                 // 158*64

// weight scratch offsets (floats): TRANSPOSED tf32-rounded copies Wt[N][K]
#define W1_OFF  0                     // 512*256 = 131072
#define W2_OFF  131072                // 512*512 = 262144
#define W3_OFF  393216                // 128*512 = 65536
#define WC1_OFF 458752                // 128*128 = 16384 (rows 64..127 zero)
#define W_TOT   475136

// ---------------- device scratch ----------------
__device__ __align__(16) float g_bufA[(size_t)N_NODES * F1];
__device__ __align__(16) float g_bufB[(size_t)M_PAD * F1];
__device__ __align__(16) float g_Wr[W_TOT];
__device__ __align__(16) float g_als[N_NODES * HH];
__device__ __align__(16) float g_ald[N_NODES * HH];
__device__ int   g_deg[N_NODES];
__device__ int   g_rowptr[N_NODES + 1];
__device__ int   g_cursor[N_NODES];
__device__ int   g_colsrc[E_TOT];

// ---------------- helpers ----------------
__device__ __forceinline__ float rnatf(float x) {
    uint32_t u;
    asm("cvt.rna.tf32.f32 %0, %1;" : "=r"(u) : "f"(x));
    return __uint_as_float(u);
}

#define LDSM4(R0, R1, R2, R3, ADDR) \
    asm volatile("ldmatrix.sync.aligned.m8n8.x4.shared.b16 {%0,%1,%2,%3}, [%4];" \
        : "=r"(R0), "=r"(R1), "=r"(R2), "=r"(R3) : "r"(ADDR))

// ---------------- CSR build (dst-indexed) ----------------
__global__ void k_zero_deg() {
    int i = blockIdx.x * blockDim.x + threadIdx.x;
    if (i < N_NODES) g_deg[i] = 0;
}

__global__ void k_count(const int* __restrict__ ei) {
    int i = blockIdx.x * blockDim.x + threadIdx.x;
    if (i < E_TOT) {
        int d = (i < E_EDGES) ? ei[E_EDGES + i] : (i - E_EDGES);
        if ((unsigned)d < (unsigned)N_NODES)
            atomicAdd(&g_deg[d], 1);
    }
}

__global__ void k_scan() {
    __shared__ int wsum[32];
    const int T = 1024;
    const int CH = (N_NODES + T - 1) / T;
    int tid = threadIdx.x;
    int start = tid * CH;
    int local = 0;
    for (int i = 0; i < CH; i++) {
        int idx = start + i;
        if (idx < N_NODES) local += g_deg[idx];
    }
    int lane = tid & 31, warp = tid >> 5;
    int v = local;
    #pragma unroll
    for (int o = 1; o < 32; o <<= 1) {
        int t = __shfl_up_sync(0xFFFFFFFFu, v, o);
        if (lane >= o) v += t;
    }
    if (lane == 31) wsum[warp] = v;
    __syncthreads();
    if (warp == 0) {
        int w = wsum[lane];
        #pragma unroll
        for (int o = 1; o < 32; o <<= 1) {
            int t = __shfl_up_sync(0xFFFFFFFFu, w, o);
            if (lane >= o) w += t;
        }
        wsum[lane] = w;
    }
    __syncthreads();
    int incl = v + (warp > 0 ? wsum[warp - 1] : 0);
    int run = incl - local;
    for (int i = 0; i < CH; i++) {
        int idx = start + i;
        if (idx < N_NODES) {
            g_rowptr[idx] = run;
            g_cursor[idx] = run;
            run += g_deg[idx];
        }
    }
    if (tid == T - 1) g_rowptr[N_NODES] = run;
}

__global__ void k_fill(const int* __restrict__ ei) {
    int i = blockIdx.x * blockDim.x + threadIdx.x;
    if (i < E_TOT) {
        int s, d;
        if (i < E_EDGES) { s = ei[i]; d = ei[E_EDGES + i]; }
        else             { s = i - E_EDGES; d = s; }
        if ((unsigned)d >= (unsigned)N_NODES) return;
        if ((unsigned)s >= (unsigned)N_NODES) s = 0;
        int pos = atomicAdd(&g_cursor[d], 1);
        if (pos < E_TOT) g_colsrc[pos] = s;
    }
}

// ---------------- weight transpose + tf32 round: g_Wr holds Wt[N][K] ----------------
__global__ void k_trans_all(const float* __restrict__ W1,
                            const float* __restrict__ W2,
                            const float* __restrict__ W3,
                            const float* __restrict__ Wc1) {
    __shared__ float t[32][33];
    int b = blockIdx.x;
    const float* src; int K, N, realN, off, ktiles;
    if (b < 128)      { src = W1;  K = 256; N = 512; realN = 512; off = W1_OFF;  ktiles = 8;  }
    else if (b < 384) { src = W2;  K = 512; N = 512; realN = 512; off = W2_OFF;  ktiles = 16; b -= 128; }
    else if (b < 448) { src = W3;  K = 512; N = 128; realN = 128; off = W3_OFF;  ktiles = 16; b -= 384; }
    else              { src = Wc1; K = 128; N = 128; realN = 64;  off = WC1_OFF; ktiles = 4;  b -= 448; }
    int kb = (b % ktiles) * 32, nb = (b / ktiles) * 32;
    int tx = threadIdx.x, ty = threadIdx.y;   // 32 x 8
    #pragma unroll
    for (int i = ty; i < 32; i += 8) {
        int k = kb + i, n = nb + tx;
        float v = 0.f;
        if (k < K && n < realN) v = src[(size_t)k * realN + n];
        t[i][tx] = rnatf(v);
    }
    __syncthreads();
    #pragma unroll
    for (int i = ty; i < 32; i += 8) {
        int n = nb + i, k = kb + tx;
        if (n < N && k < K) g_Wr[off + (size_t)n * K + k] = t[tx][i];
    }
}

__global__ void k_round_x(const float* __restrict__ x) {
    int i = blockIdx.x * blockDim.x + threadIdx.x;
    if (i >= N_NODES * FIN / 4) return;
    float4 v = ((const float4*)x)[i];
    ((float4*)g_bufB)[i] = make_float4(rnatf(v.x), rnatf(v.y), rnatf(v.z), rnatf(v.w));
}

// ---------------- tf32 tensor-core GEMM (ldmatrix path, BM=64, 3 CTAs/SM) ----------------
// C[M,N] = A[M,K] @ B[K,N]; A = g_bufB (tf32, padded rows), B = g_Wr+woff as Wt[N][K].
// Block tile 64x128, BK=16, 8 warps (2M x 4N), warp tile 32x32 (MFRAG=2).
// Fused attn epilogue when as != nullptr (blockIdx.x = head, N must be 128).
#define MFRAG 2
#define BM    64
#define GBN   128
#define GBK   16
#define SMS   20   // smem row stride (floats): 20r mod 32 spans all banks over 8 rows

__device__ __forceinline__ void mma_tf32(float c[4], uint32_t a0, uint32_t a1,
                                         uint32_t a2, uint32_t a3,
                                         uint32_t b0, uint32_t b1) {
    asm volatile(
        "mma.sync.aligned.m16n8k8.row.col.f32.tf32.tf32.f32 "
        "{%0,%1,%2,%3}, {%4,%5,%6,%7}, {%8,%9}, {%0,%1,%2,%3};"
        : "+f"(c[0]), "+f"(c[1]), "+f"(c[2]), "+f"(c[3])
        : "r"(a0), "r"(a1), "r"(a2), "r"(a3), "r"(b0), "r"(b1));
}

__global__ __launch_bounds__(256, 3) void k_gemm_tc(int M, int K, int N, int woff,
                                                    const float* __restrict__ as,
                                                    const float* __restrict__ ad) {
    const float* __restrict__ A  = g_bufB;
    const float* __restrict__ Bt = g_Wr + woff;      // [N][K]
    float* __restrict__ C = g_bufA;

    __shared__ __align__(16) float As[2][BM][SMS];
    __shared__ __align__(16) float Bs[2][GBN][SMS];
    __shared__ __align__(16) float as_sm[GBN], ad_sm[GBN];
    __shared__ float red_s[BM][4], red_d[BM][4];

    const uint32_t ASTG = BM * SMS * 4;
    const uint32_t BSTG = GBN * SMS * 4;

    int tid  = threadIdx.x;
    int warp = tid >> 5;
    int lane = tid & 31;
    int wm = warp >> 2;          // 0..1
    int wn = warp & 3;           // 0..3
    int sub = lane >> 3, rr = lane & 7;

    int m0 = blockIdx.y * BM;
    int n0 = blockIdx.x * GBN;

    if (as != nullptr && tid < 32) {
        ((float4*)as_sm)[tid] = ((const float4*)(as + blockIdx.x * HD))[tid];
        ((float4*)ad_sm)[tid] = ((const float4*)(ad + blockIdx.x * HD))[tid];
    }

    uint32_t aBase = (uint32_t)__cvta_generic_to_shared(&As[0][0][0]);
    uint32_t bBase = (uint32_t)__cvta_generic_to_shared(&Bs[0][0][0]);
    uint32_t aAddr[MFRAG], bAddr[2];
    #pragma unroll
    for (int mf = 0; mf < MFRAG; mf++)
        aAddr[mf] = aBase + (((wm * (MFRAG * 16) + mf * 16 + (sub & 1) * 8 + rr) * SMS
                              + (sub >> 1) * 4) << 2);
    #pragma unroll
    for (int p = 0; p < 2; p++)
        bAddr[p] = bBase + (((wn * 32 + p * 16 + ((sub >> 1) & 1) * 8 + rr) * SMS
                             + (sub & 1) * 4) << 2);

    float acc[MFRAG][4][4];
    #pragma unroll
    for (int i = 0; i < MFRAG; i++)
        #pragma unroll
        for (int j = 0; j < 4; j++)
            #pragma unroll
            for (int r = 0; r < 4; r++) acc[i][j][r] = 0.f;

    auto load_stage = [&](int s, int k0) {
        // A tile: BM rows x 16 floats = BM*4 16B chunks (256 for BM=64)
        {
            int i = tid;   // exactly 256 chunks
            int row = i >> 2, c4 = i & 3;
            const float* ga = A + (size_t)(m0 + row) * K + k0 + c4 * 4;
            uint32_t da = (uint32_t)__cvta_generic_to_shared(&As[s][row][c4 * 4]);
            asm volatile("cp.async.cg.shared.global [%0], [%1], 16;" :: "r"(da), "l"(ga));
        }
        // B tile: 128 n-rows x 16 floats = 512 chunks
        #pragma unroll
        for (int r = 0; r < 2; r++) {
            int i = tid + r * 256;
            int row = i >> 2, c4 = i & 3;
            const float* gb = Bt + (size_t)(n0 + row) * K + k0 + c4 * 4;
            uint32_t db = (uint32_t)__cvta_generic_to_shared(&Bs[s][row][c4 * 4]);
            asm volatile("cp.async.cg.shared.global [%0], [%1], 16;" :: "r"(db), "l"(gb));
        }
    };

    const int nT = K / GBK;
    load_stage(0, 0);
    asm volatile("cp.async.commit_group;");

    for (int t = 0; t < nT; t++) {
        if (t + 1 < nT) {
            load_stage((t + 1) & 1, (t + 1) * GBK);
            asm volatile("cp.async.commit_group;");
            asm volatile("cp.async.wait_group 1;");
        } else {
            asm volatile("cp.async.wait_group 0;");
        }
        __syncthreads();

        uint32_t aO = (t & 1) * ASTG, bO = (t & 1) * BSTG;
        #pragma unroll
        for (int kc = 0; kc < GBK; kc += 8) {
            uint32_t af[MFRAG][4];
            #pragma unroll
            for (int mf = 0; mf < MFRAG; mf++)
                LDSM4(af[mf][0], af[mf][1], af[mf][2], af[mf][3],
                      aAddr[mf] + aO + kc * 4);
            uint32_t bf[4][2];
            LDSM4(bf[0][0], bf[0][1], bf[1][0], bf[1][1], bAddr[0] + bO + kc * 4);
            LDSM4(bf[2][0], bf[2][1], bf[3][0], bf[3][1], bAddr[1] + bO + kc * 4);
            #pragma unroll
            for (int mf = 0; mf < MFRAG; mf++)
                #pragma unroll
                for (int nf = 0; nf < 4; nf++)
                    mma_tf32(acc[mf][nf], af[mf][0], af[mf][1], af[mf][2], af[mf][3],
                             bf[nf][0], bf[nf][1]);
        }
        __syncthreads();
    }

    int g = lane >> 2, t4 = lane & 3;

    // epilogue 1: store C
    #pragma unroll
    for (int mf = 0; mf < MFRAG; mf++) {
        int r0 = m0 + wm * (MFRAG * 16) + mf * 16 + g;
        int r1 = r0 + 8;
        #pragma unroll
        for (int nf = 0; nf < 4; nf++) {
            int c = n0 + wn * 32 + nf * 8 + t4 * 2;
            if (r0 < M) {
                C[(size_t)r0 * N + c]     = acc[mf][nf][0];
                C[(size_t)r0 * N + c + 1] = acc[mf][nf][1];
            }
            if (r1 < M) {
                C[(size_t)r1 * N + c]     = acc[mf][nf][2];
                C[(size_t)r1 * N + c + 1] = acc[mf][nf][3];
            }
        }
    }

    // epilogue 2: fused attention coefficients
    if (as != nullptr) {
        #pragma unroll
        for (int mf = 0; mf < MFRAG; mf++) {
            float ps0 = 0.f, pd0 = 0.f, ps1 = 0.f, pd1 = 0.f;
            #pragma unroll
            for (int nf = 0; nf < 4; nf++) {
                int c = wn * 32 + nf * 8 + t4 * 2;
                float a0 = as_sm[c], a1 = as_sm[c + 1];
                float d0 = ad_sm[c], d1 = ad_sm[c + 1];
                ps0 += acc[mf][nf][0] * a0 + acc[mf][nf][1] * a1;
                pd0 += acc[mf][nf][0] * d0 + acc[mf][nf][1] * d1;
                ps1 += acc[mf][nf][2] * a0 + acc[mf][nf][3] * a1;
                pd1 += acc[mf][nf][2] * d0 + acc[mf][nf][3] * d1;
            }
            ps0 += __shfl_xor_sync(0xFFFFFFFFu, ps0, 1);
            ps0 += __shfl_xor_sync(0xFFFFFFFFu, ps0, 2);
            pd0 += __shfl_xor_sync(0xFFFFFFFFu, pd0, 1);
            pd0 += __shfl_xor_sync(0xFFFFFFFFu, pd0, 2);
            ps1 += __shfl_xor_sync(0xFFFFFFFFu, ps1, 1);
            ps1 += __shfl_xor_sync(0xFFFFFFFFu, ps1, 2);
            pd1 += __shfl_xor_sync(0xFFFFFFFFu, pd1, 1);
            pd1 += __shfl_xor_sync(0xFFFFFFFFu, pd1, 2);
            if (t4 == 0) {
                int r0 = wm * (MFRAG * 16) + mf * 16 + g;
                red_s[r0][wn] = ps0;  red_d[r0][wn] = pd0;
                red_s[r0 + 8][wn] = ps1;  red_d[r0 + 8][wn] = pd1;
            }
        }
        __syncthreads();
        if (tid < BM) {
            int node = m0 + tid;
            if (node < M) {
                float s = red_s[tid][0] + red_s[tid][1] + red_s[tid][2] + red_s[tid][3];
                float d = red_d[tid][0] + red_d[tid][1] + red_d[tid][2] + red_d[tid][3];
                int H = gridDim.x;
                g_als[node * H + blockIdx.x] = s;
                g_ald[node * H + blockIdx.x] = d;
            }
        }
    }
}

// ---------------- segment-softmax aggregation (online softmax) ----------------
__global__ void k_aggregate(const float* __restrict__ bias,
                            float* __restrict__ outExt,
                            int H, int applyElu, int outSel) {
    int gw = (blockIdx.x * blockDim.x + threadIdx.x) >> 5;
    int lane = threadIdx.x & 31;
    int node = gw / H, head = gw - node * H;
    if (node >= N_NODES) return;
    int beg = g_rowptr[node], end = g_rowptr[node + 1];
    float ad = g_ald[node * H + head];
    const int F = H * HD;

    float m = -1e30f, denom = 0.f;
    float4 acc = make_float4(0.f, 0.f, 0.f, 0.f);
    int s_next = (beg < end) ? g_colsrc[beg] : 0;
    for (int j = beg; j < end; j++) {
        int s = s_next;
        if (j + 1 < end) s_next = g_colsrc[j + 1];
        float e = g_als[s * H + head] + ad;
        e = (e > 0.f) ? e : 0.2f * e;
        if (e > m) {
            float sc = __expf(m - e);
            denom *= sc;
            acc.x *= sc; acc.y *= sc; acc.z *= sc; acc.w *= sc;
            m = e;
        }
        float p = __expf(e - m);
        denom += p;
        float4 v = *(const float4*)(g_bufA + (size_t)s * F + head * HD + lane * 4);
        acc.x += p * v.x; acc.y += p * v.y; acc.z += p * v.z; acc.w += p * v.w;
    }
    float inv = 1.f / (denom + 1e-16f);
    float4 b = *(const float4*)(bias + head * HD + lane * 4);
    float o0 = acc.x * inv + b.x;
    float o1 = acc.y * inv + b.y;
    float o2 = acc.z * inv + b.z;
    float o3 = acc.w * inv + b.w;
    if (applyElu) {
        o0 = (o0 > 0.f) ? o0 : expm1f(o0);
        o1 = (o1 > 0.f) ? o1 : expm1f(o1);
        o2 = (o2 > 0.f) ? o2 : expm1f(o2);
        o3 = (o3 > 0.f) ? o3 : expm1f(o3);
    }
    size_t idx = (size_t)node * F + head * HD + lane * 4;
    if (outSel) {
        *(float4*)(outExt + idx) = make_float4(o0, o1, o2, o3);
        *(float4*)(g_bufB + idx) =
            make_float4(rnatf(o0), rnatf(o1), rnatf(o2), rnatf(o3));
    } else {
        *(float4*)(g_bufB + idx) =
            make_float4(rnatf(o0), rnatf(o1), rnatf(o2), rnatf(o3));
    }
}

// ---------------- classifier finisher ----------------
__global__ void k_cls2(const float* __restrict__ bc1,
                       const float* __restrict__ Wc2,
                       const float* __restrict__ bc2,
                       float* __restrict__ out) {
    int gw = (blockIdx.x * blockDim.x + threadIdx.x) >> 5;
    int lane = threadIdx.x & 31;
    if (gw >= N_NODES) return;
    float h0 = g_bufA[(size_t)gw * 128 + lane];
    float h1 = g_bufA[(size_t)gw * 128 + lane + 32];
    h0 = fmaxf(h0 + bc1[lane], 0.f);
    h1 = fmaxf(h1 + bc1[lane + 32], 0.f);
    float o0 = h0 * Wc2[lane * 2]     + h1 * Wc2[(lane + 32) * 2];
    float o1 = h0 * Wc2[lane * 2 + 1] + h1 * Wc2[(lane + 32) * 2 + 1];
    #pragma unroll
    for (int o = 16; o; o >>= 1) {
        o0 += __shfl_xor_sync(0xFFFFFFFFu, o0, o);
        o1 += __shfl_xor_sync(0xFFFFFFFFu, o1, o);
    }
    if (lane == 0) {
        out[gw * 2]     = o0 + bc2[0];
        out[gw * 2 + 1] = o1 + bc2[1];
    }
}

// ---------------- launch: kernel launches ONLY ----------------
extern "C" void kernel_launch(void* const* d_in, const int* in_sizes, int n_in,
                              void* d_out, int out_size) {
    const float* x   = (const float*)d_in[0];
    const int*   ei  = (const int*)  d_in[1];
    const float* W1  = (const float*)d_in[2];
    const float* a1s = (const float*)d_in[3];
    const float* a1d = (const float*)d_in[4];
    const float* b1  = (const float*)d_in[5];
    const float* W2  = (const float*)d_in[6];
    const float* a2s = (const float*)d_in[7];
    const float* a2d = (const float*)d_in[8];
    const float* b2  = (const float*)d_in[9];
    const float* W3  = (const float*)d_in[10];
    const float* a3s = (const float*)d_in[11];
    const float* a3d = (const float*)d_in[12];
    const float* b3  = (const float*)d_in[13];
    const float* Wc1 = (const float*)d_in[14];
    const float* bc1 = (const float*)d_in[15];
    const float* Wc2 = (const float*)d_in[16];
    const float* bc2 = (const float*)d_in[17];

    float* out = (float*)d_out;                 // [N,2]
    float* emb = out + (size_t)N_NODES * 2;     // [N,128]

    dim3 gT(256);
    const int blocksH4 = (N_NODES * HH + 7) / 8;
    const int blocksH1 = (N_NODES * 1  + 7) / 8;
    const int gy = M_PAD / BM;     // 158

    // prep (3 launches, keeps L1 GEMM in the ncu-profiled slot)
    k_trans_all<<<464, dim3(32, 8)>>>(W1, W2, W3, Wc1);
    k_round_x<<<(N_NODES * FIN / 4 + 255) / 256, 256>>>(x);
    k_zero_deg<<<(N_NODES + 255) / 256, 256>>>();

    // ---- layer 1 GEMM (+fused attn) ----
    k_gemm_tc<<<dim3(F1 / GBN, gy), gT>>>(N_NODES, FIN, F1, W1_OFF, a1s, a1d);

    // CSR build
    k_count<<<(E_TOT + 255) / 256, 256>>>(ei);
    k_scan <<<1, 1024>>>();
    k_fill <<<(E_TOT + 255) / 256, 256>>>(ei);

    // ---- layer 1 aggregate -> bufB (ELU, tf32) ----
    k_aggregate<<<blocksH4, gT>>>(b1, nullptr, HH, 1, 0);

    // ---- layer 2 ----
    k_gemm_tc<<<dim3(F1 / GBN, gy), gT>>>(N_NODES, F1, F1, W2_OFF, a2s, a2d);
    k_aggregate<<<blocksH4, gT>>>(b2, nullptr, HH, 1, 0);

    // ---- layer 3 (H=1) ----
    k_gemm_tc<<<dim3(HD / GBN, gy), gT>>>(N_NODES, F1, HD, W3_OFF, a3s, a3d);
    k_aggregate<<<blocksH1, gT>>>(b3, emb, 1, 0, 1);

    // ---- classifier ----
    k_gemm_tc<<<dim3(1, gy), gT>>>(N_NODES, HD, 128, WC1_OFF, nullptr, nullptr);
    k_cls2<<<blocksH1, gT>>>(bc1, Wc2, bc2, out);
}

// round 15
// speedup vs baseline: 1.4851x; 1.4851x over previous
#include <cuda_runtime.h>
#include <cuda_fp16.h>
#include <math.h>
#include <stdint.h>

// ---------------- problem constants ----------------
#define N_NODES 10000
#define E_EDGES 320000
#define E_TOT   (E_EDGES + N_NODES)   // with self-loops
#define FIN     256
#define HD      128                   // channels per head
#define HH      4                     // heads (layers 1,2)
#define F1      (HH * HD)             // 512
#define M_PAD   10112                 // 79*128 = 158*64

// weight scratch offsets (floats): TRANSPOSED tf32-rounded copies Wt[N][K]
#define W1_OFF  0                     // 512*256 = 131072
#define W2_OFF  131072                // 512*512 = 262144
#define W3_OFF  393216                // 128*512 = 65536
#define WC1_OFF 458752                // 128*128 = 16384 (rows 64..127 zero)
#define W_TOT   475136

// ---------------- device scratch ----------------
__device__ __align__(16) __half g_bufH[(size_t)N_NODES * F1];  // GEMM C, fp16 (10 MB)
__device__ __align__(16) float g_bufB[(size_t)M_PAD * F1];     // GEMM A (tf32, padded)
__device__ __align__(16) float g_Wr[W_TOT];
__device__ __align__(16) float g_als[N_NODES * HH];
__device__ __align__(16) float g_ald[N_NODES * HH];
__device__ int   g_deg[N_NODES];
__device__ int   g_rowptr[N_NODES + 1];
__device__ int   g_cursor[N_NODES];
__device__ int   g_colsrc[E_TOT];

// ---------------- helpers ----------------
__device__ __forceinline__ float rnatf(float x) {
    uint32_t u;
    asm("cvt.rna.tf32.f32 %0, %1;" : "=r"(u) : "f"(x));
    return __uint_as_float(u);
}

#define LDSM4(R0, R1, R2, R3, ADDR) \
    asm volatile("ldmatrix.sync.aligned.m8n8.x4.shared.b16 {%0,%1,%2,%3}, [%4];" \
        : "=r"(R0), "=r"(R1), "=r"(R2), "=r"(R3) : "r"(ADDR))

// ---------------- CSR build (dst-indexed) ----------------
__global__ void k_zero_deg() {
    int i = blockIdx.x * blockDim.x + threadIdx.x;
    if (i < N_NODES) g_deg[i] = 0;
}

__global__ void k_count(const int* __restrict__ ei) {
    int i = blockIdx.x * blockDim.x + threadIdx.x;
    if (i < E_TOT) {
        int d = (i < E_EDGES) ? ei[E_EDGES + i] : (i - E_EDGES);
        if ((unsigned)d < (unsigned)N_NODES)
            atomicAdd(&g_deg[d], 1);
    }
}

__global__ void k_scan() {
    __shared__ int wsum[32];
    const int T = 1024;
    const int CH = (N_NODES + T - 1) / T;
    int tid = threadIdx.x;
    int start = tid * CH;
    int local = 0;
    for (int i = 0; i < CH; i++) {
        int idx = start + i;
        if (idx < N_NODES) local += g_deg[idx];
    }
    int lane = tid & 31, warp = tid >> 5;
    int v = local;
    #pragma unroll
    for (int o = 1; o < 32; o <<= 1) {
        int t = __shfl_up_sync(0xFFFFFFFFu, v, o);
        if (lane >= o) v += t;
    }
    if (lane == 31) wsum[warp] = v;
    __syncthreads();
    if (warp == 0) {
        int w = wsum[lane];
        #pragma unroll
        for (int o = 1; o < 32; o <<= 1) {
            int t = __shfl_up_sync(0xFFFFFFFFu, w, o);
            if (lane >= o) w += t;
        }
        wsum[lane] = w;
    }
    __syncthreads();
    int incl = v + (warp > 0 ? wsum[warp - 1] : 0);
    int run = incl - local;
    for (int i = 0; i < CH; i++) {
        int idx = start + i;
        if (idx < N_NODES) {
            g_rowptr[idx] = run;
            g_cursor[idx] = run;
            run += g_deg[idx];
        }
    }
    if (tid == T - 1) g_rowptr[N_NODES] = run;
}

__global__ void k_fill(const int* __restrict__ ei) {
    int i = blockIdx.x * blockDim.x + threadIdx.x;
    if (i < E_TOT) {
        int s, d;
        if (i < E_EDGES) { s = ei[i]; d = ei[E_EDGES + i]; }
        else             { s = i - E_EDGES; d = s; }
        if ((unsigned)d >= (unsigned)N_NODES) return;
        if ((unsigned)s >= (unsigned)N_NODES) s = 0;
        int pos = atomicAdd(&g_cursor[d], 1);
        if (pos < E_TOT) g_colsrc[pos] = s;
    }
}

// ---------------- weight transpose + tf32 round: g_Wr holds Wt[N][K] ----------------
__global__ void k_trans_all(const float* __restrict__ W1,
                            const float* __restrict__ W2,
                            const float* __restrict__ W3,
                            const float* __restrict__ Wc1) {
    __shared__ float t[32][33];
    int b = blockIdx.x;
    const float* src; int K, N, realN, off, ktiles;
    if (b < 128)      { src = W1;  K = 256; N = 512; realN = 512; off = W1_OFF;  ktiles = 8;  }
    else if (b < 384) { src = W2;  K = 512; N = 512; realN = 512; off = W2_OFF;  ktiles = 16; b -= 128; }
    else if (b < 448) { src = W3;  K = 512; N = 128; realN = 128; off = W3_OFF;  ktiles = 16; b -= 384; }
    else              { src = Wc1; K = 128; N = 128; realN = 64;  off = WC1_OFF; ktiles = 4;  b -= 448; }
    int kb = (b % ktiles) * 32, nb = (b / ktiles) * 32;
    int tx = threadIdx.x, ty = threadIdx.y;   // 32 x 8
    #pragma unroll
    for (int i = ty; i < 32; i += 8) {
        int k = kb + i, n = nb + tx;
        float v = 0.f;
        if (k < K && n < realN) v = src[(size_t)k * realN + n];
        t[i][tx] = rnatf(v);
    }
    __syncthreads();
    #pragma unroll
    for (int i = ty; i < 32; i += 8) {
        int n = nb + i, k = kb + tx;
        if (n < N && k < K) g_Wr[off + (size_t)n * K + k] = t[tx][i];
    }
}

__global__ void k_round_x(const float* __restrict__ x) {
    int i = blockIdx.x * blockDim.x + threadIdx.x;
    if (i >= N_NODES * FIN / 4) return;
    float4 v = ((const float4*)x)[i];
    ((float4*)g_bufB)[i] = make_float4(rnatf(v.x), rnatf(v.y), rnatf(v.z), rnatf(v.w));
}

// ---------------- tf32 tensor-core GEMM (ldmatrix path) ----------------
// C[M,N] = A[M,K] @ B[K,N]; A = g_bufB (tf32, padded rows), B = g_Wr+woff as Wt[N][K].
// C stored fp16 to g_bufH. Block (MFRAG*32) x 128, BK=16, 8 warps (2M x 4N).
// Fused attn epilogue (fp32 accumulators) when as != nullptr.
#define GBN 128
#define GBK 16
#define SMS 20

__device__ __forceinline__ void mma_tf32(float c[4], uint32_t a0, uint32_t a1,
                                         uint32_t a2, uint32_t a3,
                                         uint32_t b0, uint32_t b1) {
    asm volatile(
        "mma.sync.aligned.m16n8k8.row.col.f32.tf32.tf32.f32 "
        "{%0,%1,%2,%3}, {%4,%5,%6,%7}, {%8,%9}, {%0,%1,%2,%3};"
        : "+f"(c[0]), "+f"(c[1]), "+f"(c[2]), "+f"(c[3])
        : "r"(a0), "r"(a1), "r"(a2), "r"(a3), "r"(b0), "r"(b1));
}

template<int MFRAG>
__global__ __launch_bounds__(256, 2) void k_gemm_tc(int M, int K, int N, int woff,
                                                    const float* __restrict__ as,
                                                    const float* __restrict__ ad) {
    const int BM = MFRAG * 32;
    const float* __restrict__ A  = g_bufB;
    const float* __restrict__ Bt = g_Wr + woff;      // [N][K]
    __half* __restrict__ C = g_bufH;

    __shared__ __align__(16) float As[2][MFRAG * 32][SMS];
    __shared__ __align__(16) float Bs[2][GBN][SMS];
    __shared__ __align__(16) float as_sm[GBN], ad_sm[GBN];
    __shared__ float red_s[MFRAG * 32][4], red_d[MFRAG * 32][4];

    const uint32_t ASTG = BM * SMS * 4;
    const uint32_t BSTG = GBN * SMS * 4;

    int tid  = threadIdx.x;
    int warp = tid >> 5;
    int lane = tid & 31;
    int wm = warp >> 2;
    int wn = warp & 3;
    int sub = lane >> 3, rr = lane & 7;

    int m0 = blockIdx.y * BM;
    int n0 = blockIdx.x * GBN;

    if (as != nullptr && tid < 32) {
        ((float4*)as_sm)[tid] = ((const float4*)(as + blockIdx.x * HD))[tid];
        ((float4*)ad_sm)[tid] = ((const float4*)(ad + blockIdx.x * HD))[tid];
    }

    uint32_t aBase = (uint32_t)__cvta_generic_to_shared(&As[0][0][0]);
    uint32_t bBase = (uint32_t)__cvta_generic_to_shared(&Bs[0][0][0]);
    uint32_t aAddr[MFRAG], bAddr[2];
    #pragma unroll
    for (int mf = 0; mf < MFRAG; mf++)
        aAddr[mf] = aBase + (((wm * (MFRAG * 16) + mf * 16 + (sub & 1) * 8 + rr) * SMS
                              + (sub >> 1) * 4) << 2);
    #pragma unroll
    for (int p = 0; p < 2; p++)
        bAddr[p] = bBase + (((wn * 32 + p * 16 + ((sub >> 1) & 1) * 8 + rr) * SMS
                             + (sub & 1) * 4) << 2);

    float acc[MFRAG][4][4];
    #pragma unroll
    for (int i = 0; i < MFRAG; i++)
        #pragma unroll
        for (int j = 0; j < 4; j++)
            #pragma unroll
            for (int r = 0; r < 4; r++) acc[i][j][r] = 0.f;

    auto load_stage = [&](int s, int k0) {
        for (int i = tid; i < BM * 4; i += 256) {
            int row = i >> 2, c4 = i & 3;
            const float* ga = A + (size_t)(m0 + row) * K + k0 + c4 * 4;
            uint32_t da = (uint32_t)__cvta_generic_to_shared(&As[s][row][c4 * 4]);
            asm volatile("cp.async.cg.shared.global [%0], [%1], 16;" :: "r"(da), "l"(ga));
        }
        for (int i = tid; i < GBN * 4; i += 256) {
            int row = i >> 2, c4 = i & 3;
            const float* gb = Bt + (size_t)(n0 + row) * K + k0 + c4 * 4;
            uint32_t db = (uint32_t)__cvta_generic_to_shared(&Bs[s][row][c4 * 4]);
            asm volatile("cp.async.cg.shared.global [%0], [%1], 16;" :: "r"(db), "l"(gb));
        }
    };

    const int nT = K / GBK;
    load_stage(0, 0);
    asm volatile("cp.async.commit_group;");

    for (int t = 0; t < nT; t++) {
        if (t + 1 < nT) {
            load_stage((t + 1) & 1, (t + 1) * GBK);
            asm volatile("cp.async.commit_group;");
            asm volatile("cp.async.wait_group 1;");
        } else {
            asm volatile("cp.async.wait_group 0;");
        }
        __syncthreads();

        uint32_t aO = (t & 1) * ASTG, bO = (t & 1) * BSTG;
        #pragma unroll
        for (int kc = 0; kc < GBK; kc += 8) {
            uint32_t af[MFRAG][4];
            #pragma unroll
            for (int mf = 0; mf < MFRAG; mf++)
                LDSM4(af[mf][0], af[mf][1], af[mf][2], af[mf][3],
                      aAddr[mf] + aO + kc * 4);
            uint32_t bf[4][2];
            LDSM4(bf[0][0], bf[0][1], bf[1][0], bf[1][1], bAddr[0] + bO + kc * 4);
            LDSM4(bf[2][0], bf[2][1], bf[3][0], bf[3][1], bAddr[1] + bO + kc * 4);
            #pragma unroll
            for (int mf = 0; mf < MFRAG; mf++)
                #pragma unroll
                for (int nf = 0; nf < 4; nf++)
                    mma_tf32(acc[mf][nf], af[mf][0], af[mf][1], af[mf][2], af[mf][3],
                             bf[nf][0], bf[nf][1]);
        }
        __syncthreads();
    }

    int g = lane >> 2, t4 = lane & 3;

    // epilogue 1: store C as fp16 (half2 per register pair)
    #pragma unroll
    for (int mf = 0; mf < MFRAG; mf++) {
        int r0 = m0 + wm * (MFRAG * 16) + mf * 16 + g;
        int r1 = r0 + 8;
        #pragma unroll
        for (int nf = 0; nf < 4; nf++) {
            int c = n0 + wn * 32 + nf * 8 + t4 * 2;
            if (r0 < M)
                *(__half2*)(C + (size_t)r0 * N + c) =
                    __floats2half2_rn(acc[mf][nf][0], acc[mf][nf][1]);
            if (r1 < M)
                *(__half2*)(C + (size_t)r1 * N + c) =
                    __floats2half2_rn(acc[mf][nf][2], acc[mf][nf][3]);
        }
    }

    // epilogue 2: fused attention coefficients (exact fp32 accumulators)
    if (as != nullptr) {
        #pragma unroll
        for (int mf = 0; mf < MFRAG; mf++) {
            float ps0 = 0.f, pd0 = 0.f, ps1 = 0.f, pd1 = 0.f;
            #pragma unroll
            for (int nf = 0; nf < 4; nf++) {
                int c = wn * 32 + nf * 8 + t4 * 2;
                float a0 = as_sm[c], a1 = as_sm[c + 1];
                float d0 = ad_sm[c], d1 = ad_sm[c + 1];
                ps0 += acc[mf][nf][0] * a0 + acc[mf][nf][1] * a1;
                pd0 += acc[mf][nf][0] * d0 + acc[mf][nf][1] * d1;
                ps1 += acc[mf][nf][2] * a0 + acc[mf][nf][3] * a1;
                pd1 += acc[mf][nf][2] * d0 + acc[mf][nf][3] * d1;
            }
            ps0 += __shfl_xor_sync(0xFFFFFFFFu, ps0, 1);
            ps0 += __shfl_xor_sync(0xFFFFFFFFu, ps0, 2);
            pd0 += __shfl_xor_sync(0xFFFFFFFFu, pd0, 1);
            pd0 += __shfl_xor_sync(0xFFFFFFFFu, pd0, 2);
            ps1 += __shfl_xor_sync(0xFFFFFFFFu, ps1, 1);
            ps1 += __shfl_xor_sync(0xFFFFFFFFu, ps1, 2);
            pd1 += __shfl_xor_sync(0xFFFFFFFFu, pd1, 1);
            pd1 += __shfl_xor_sync(0xFFFFFFFFu, pd1, 2);
            if (t4 == 0) {
                int r0 = wm * (MFRAG * 16) + mf * 16 + g;
                red_s[r0][wn] = ps0;  red_d[r0][wn] = pd0;
                red_s[r0 + 8][wn] = ps1;  red_d[r0 + 8][wn] = pd1;
            }
        }
        __syncthreads();
        if (tid < BM) {
            int node = m0 + tid;
            if (node < M) {
                float s = red_s[tid][0] + red_s[tid][1] + red_s[tid][2] + red_s[tid][3];
                float d = red_d[tid][0] + red_d[tid][1] + red_d[tid][2] + red_d[tid][3];
                int H = gridDim.x;
                g_als[node * H + blockIdx.x] = s;
                g_ald[node * H + blockIdx.x] = d;
            }
        }
    }
}

// ---------------- segment-softmax aggregation (online softmax, fp16 gather) ----------------
__global__ void k_aggregate(const float* __restrict__ bias,
                            float* __restrict__ outExt,
                            int H, int applyElu, int outSel) {
    int gw = (blockIdx.x * blockDim.x + threadIdx.x) >> 5;
    int lane = threadIdx.x & 31;
    int node = gw / H, head = gw - node * H;
    if (node >= N_NODES) return;
    int beg = g_rowptr[node], end = g_rowptr[node + 1];
    float ad = g_ald[node * H + head];
    const int F = H * HD;

    float m = -1e30f, denom = 0.f;
    float4 acc = make_float4(0.f, 0.f, 0.f, 0.f);
    int s_next = (beg < end) ? g_colsrc[beg] : 0;
    for (int j = beg; j < end; j++) {
        int s = s_next;
        if (j + 1 < end) s_next = g_colsrc[j + 1];
        float e = g_als[s * H + head] + ad;
        e = (e > 0.f) ? e : 0.2f * e;
        if (e > m) {
            float sc = __expf(m - e);
            denom *= sc;
            acc.x *= sc; acc.y *= sc; acc.z *= sc; acc.w *= sc;
            m = e;
        }
        float p = __expf(e - m);
        denom += p;
        // gather 4 features as 2x half2 (one 8B load)
        const uint2 hv = *(const uint2*)(g_bufH + (size_t)s * F + head * HD + lane * 4);
        float2 f01 = __half22float2(*(const __half2*)&hv.x);
        float2 f23 = __half22float2(*(const __half2*)&hv.y);
        acc.x += p * f01.x; acc.y += p * f01.y;
        acc.z += p * f23.x; acc.w += p * f23.y;
    }
    float inv = 1.f / (denom + 1e-16f);
    float4 b = *(const float4*)(bias + head * HD + lane * 4);
    float o0 = acc.x * inv + b.x;
    float o1 = acc.y * inv + b.y;
    float o2 = acc.z * inv + b.z;
    float o3 = acc.w * inv + b.w;
    if (applyElu) {
        o0 = (o0 > 0.f) ? o0 : expm1f(o0);
        o1 = (o1 > 0.f) ? o1 : expm1f(o1);
        o2 = (o2 > 0.f) ? o2 : expm1f(o2);
        o3 = (o3 > 0.f) ? o3 : expm1f(o3);
    }
    size_t idx = (size_t)node * F + head * HD + lane * 4;
    if (outSel) {
        *(float4*)(outExt + idx) = make_float4(o0, o1, o2, o3);   // emb fp32
        *(float4*)(g_bufB + idx) =
            make_float4(rnatf(o0), rnatf(o1), rnatf(o2), rnatf(o3));  // classifier A
    } else {
        *(float4*)(g_bufB + idx) =
            make_float4(rnatf(o0), rnatf(o1), rnatf(o2), rnatf(o3));
    }
}

// ---------------- classifier finisher: out = relu(hid+bc1) @ Wc2 + bc2 ----------------
// hid = g_bufH rows of 128 fp16 (cols 64..127 exact zeros from padded Wc1)
__global__ void k_cls2(const float* __restrict__ bc1,
                       const float* __restrict__ Wc2,
                       const float* __restrict__ bc2,
                       float* __restrict__ out) {
    int gw = (blockIdx.x * blockDim.x + threadIdx.x) >> 5;
    int lane = threadIdx.x & 31;
    if (gw >= N_NODES) return;
    float h0 = __half2float(g_bufH[(size_t)gw * 128 + lane]);
    float h1 = __half2float(g_bufH[(size_t)gw * 128 + lane + 32]);
    h0 = fmaxf(h0 + bc1[lane], 0.f);
    h1 = fmaxf(h1 + bc1[lane + 32], 0.f);
    float o0 = h0 * Wc2[lane * 2]     + h1 * Wc2[(lane + 32) * 2];
    float o1 = h0 * Wc2[lane * 2 + 1] + h1 * Wc2[(lane + 32) * 2 + 1];
    #pragma unroll
    for (int o = 16; o; o >>= 1) {
        o0 += __shfl_xor_sync(0xFFFFFFFFu, o0, o);
        o1 += __shfl_xor_sync(0xFFFFFFFFu, o1, o);
    }
    if (lane == 0) {
        out[gw * 2]     = o0 + bc2[0];
        out[gw * 2 + 1] = o1 + bc2[1];
    }
}

// ---------------- launch: kernel launches ONLY ----------------
extern "C" void kernel_launch(void* const* d_in, const int* in_sizes, int n_in,
                              void* d_out, int out_size) {
    const float* x   = (const float*)d_in[0];
    const int*   ei  = (const int*)  d_in[1];
    const float* W1  = (const float*)d_in[2];
    const float* a1s = (const float*)d_in[3];
    const float* a1d = (const float*)d_in[4];
    const float* b1  = (const float*)d_in[5];
    const float* W2  = (const float*)d_in[6];
    const float* a2s = (const float*)d_in[7];
    const float* a2d = (const float*)d_in[8];
    const float* b2  = (const float*)d_in[9];
    const float* W3  = (const float*)d_in[10];
    const float* a3s = (const float*)d_in[11];
    const float* a3d = (const float*)d_in[12];
    const float* b3  = (const float*)d_in[13];
    const float* Wc1 = (const float*)d_in[14];
    const float* bc1 = (const float*)d_in[15];
    const float* Wc2 = (const float*)d_in[16];
    const float* bc2 = (const float*)d_in[17];

    float* out = (float*)d_out;                 // [N,2]
    float* emb = out + (size_t)N_NODES * 2;     // [N,128]

    dim3 gT(256);
    const int blocksH4 = (N_NODES * HH + 7) / 8;
    const int blocksH1 = (N_NODES * 1  + 7) / 8;
    const int gy4 = M_PAD / 128;   // 79
    const int gy2 = M_PAD / 64;    // 158

    // prep (3 launches, keeps L1 GEMM in the ncu-profiled slot)
    k_trans_all<<<464, dim3(32, 8)>>>(W1, W2, W3, Wc1);
    k_round_x<<<(N_NODES * FIN / 4 + 255) / 256, 256>>>(x);
    k_zero_deg<<<(N_NODES + 255) / 256, 256>>>();

    // ---- layer 1 GEMM (+fused attn) ----
    k_gemm_tc<4><<<dim3(F1 / GBN, gy4), gT>>>(N_NODES, FIN, F1, W1_OFF, a1s, a1d);

    // CSR build
    k_count<<<(E_TOT + 255) / 256, 256>>>(ei);
    k_scan <<<1, 1024>>>();
    k_fill <<<(E_TOT + 255) / 256, 256>>>(ei);

    // ---- layer 1 aggregate -> bufB (ELU, tf32) ----
    k_aggregate<<<blocksH4, gT>>>(b1, nullptr, HH, 1, 0);

    // ---- layer 2 ----
    k_gemm_tc<4><<<dim3(F1 / GBN, gy4), gT>>>(N_NODES, F1, F1, W2_OFF, a2s, a2d);
    k_aggregate<<<blocksH4, gT>>>(b2, nullptr, HH, 1, 0);

    // ---- layer 3 (H=1): BM=64 only here (grid would be 79 otherwise) ----
    k_gemm_tc<2><<<dim3(HD / GBN, gy2), gT>>>(N_NODES, F1, HD, W3_OFF, a3s, a3d);
    k_aggregate<<<blocksH1, gT>>>(b3, emb, 1, 0, 1);

    // ---- classifier ----
    k_gemm_tc<2><<<dim3(1, gy2), gT>>>(N_NODES, HD, 128, WC1_OFF, nullptr, nullptr);
    k_cls2<<<blocksH1, gT>>>(bc1, Wc2, bc2, out);
}

// round 16
// speedup vs baseline: 1.5793x; 1.0634x over previous
#include <cuda_runtime.h>
#include <cuda_fp16.h>
#include <math.h>
#include <stdint.h>

// ---------------- problem constants ----------------
#define N_NODES 10000
#define E_EDGES 320000
#define E_TOT   (E_EDGES + N_NODES)   // with self-loops
#define FIN     256
#define HD      128                   // channels per head
#define HH      4                     // heads (layers 1,2)
#define F1      (HH * HD)             // 512
#define M_PAD   10112                 // 79*128 = 158*64

// weight scratch offsets (floats): TRANSPOSED tf32-rounded copies Wt[N][K]
#define W1_OFF  0                     // 512*256 = 131072
#define W2_OFF  131072                // 512*512 = 262144
#define W3_OFF  393216                // 128*512 = 65536
#define WC1_OFF 458752                // 128*128 = 16384 (rows 64..127 zero)
#define W_TOT   475136

// ---------------- device scratch ----------------
__device__ __align__(16) __half g_bufH[(size_t)N_NODES * F1];  // GEMM C, fp16 (10 MB)
__device__ __align__(16) float g_bufB[(size_t)M_PAD * F1];     // GEMM A (tf32, padded)
__device__ __align__(16) float g_Wr[W_TOT];
__device__ __align__(16) float g_als[N_NODES * HH];
__device__ __align__(16) float g_ald[N_NODES * HH];
__device__ int   g_deg[N_NODES];
__device__ int   g_rowptr[N_NODES + 1];
__device__ int   g_cursor[N_NODES];
__device__ int   g_colsrc[E_TOT];

// ---------------- helpers ----------------
__device__ __forceinline__ float rnatf(float x) {
    uint32_t u;
    asm("cvt.rna.tf32.f32 %0, %1;" : "=r"(u) : "f"(x));
    return __uint_as_float(u);
}

__device__ __forceinline__ float lrelu(float e) { return (e > 0.f) ? e : 0.2f * e; }

#define LDSM4(R0, R1, R2, R3, ADDR) \
    asm volatile("ldmatrix.sync.aligned.m8n8.x4.shared.b16 {%0,%1,%2,%3}, [%4];" \
        : "=r"(R0), "=r"(R1), "=r"(R2), "=r"(R3) : "r"(ADDR))

// ---------------- CSR build (dst-indexed) ----------------
__global__ void k_zero_deg() {
    int i = blockIdx.x * blockDim.x + threadIdx.x;
    if (i < N_NODES) g_deg[i] = 0;
}

__global__ void k_count(const int* __restrict__ ei) {
    int i = blockIdx.x * blockDim.x + threadIdx.x;
    if (i < E_TOT) {
        int d = (i < E_EDGES) ? ei[E_EDGES + i] : (i - E_EDGES);
        if ((unsigned)d < (unsigned)N_NODES)
            atomicAdd(&g_deg[d], 1);
    }
}

__global__ void k_scan() {
    __shared__ int wsum[32];
    const int T = 1024;
    const int CH = (N_NODES + T - 1) / T;
    int tid = threadIdx.x;
    int start = tid * CH;
    int local = 0;
    for (int i = 0; i < CH; i++) {
        int idx = start + i;
        if (idx < N_NODES) local += g_deg[idx];
    }
    int lane = tid & 31, warp = tid >> 5;
    int v = local;
    #pragma unroll
    for (int o = 1; o < 32; o <<= 1) {
        int t = __shfl_up_sync(0xFFFFFFFFu, v, o);
        if (lane >= o) v += t;
    }
    if (lane == 31) wsum[warp] = v;
    __syncthreads();
    if (warp == 0) {
        int w = wsum[lane];
        #pragma unroll
        for (int o = 1; o < 32; o <<= 1) {
            int t = __shfl_up_sync(0xFFFFFFFFu, w, o);
            if (lane >= o) w += t;
        }
        wsum[lane] = w;
    }
    __syncthreads();
    int incl = v + (warp > 0 ? wsum[warp - 1] : 0);
    int run = incl - local;
    for (int i = 0; i < CH; i++) {
        int idx = start + i;
        if (idx < N_NODES) {
            g_rowptr[idx] = run;
            g_cursor[idx] = run;
            run += g_deg[idx];
        }
    }
    if (tid == T - 1) g_rowptr[N_NODES] = run;
}

__global__ void k_fill(const int* __restrict__ ei) {
    int i = blockIdx.x * blockDim.x + threadIdx.x;
    if (i < E_TOT) {
        int s, d;
        if (i < E_EDGES) { s = ei[i]; d = ei[E_EDGES + i]; }
        else             { s = i - E_EDGES; d = s; }
        if ((unsigned)d >= (unsigned)N_NODES) return;
        if ((unsigned)s >= (unsigned)N_NODES) s = 0;
        int pos = atomicAdd(&g_cursor[d], 1);
        if (pos < E_TOT) g_colsrc[pos] = s;
    }
}

// ---------------- weight transpose + tf32 round: g_Wr holds Wt[N][K] ----------------
__global__ void k_trans_all(const float* __restrict__ W1,
                            const float* __restrict__ W2,
                            const float* __restrict__ W3,
                            const float* __restrict__ Wc1) {
    __shared__ float t[32][33];
    int b = blockIdx.x;
    const float* src; int K, N, realN, off, ktiles;
    if (b < 128)      { src = W1;  K = 256; N = 512; realN = 512; off = W1_OFF;  ktiles = 8;  }
    else if (b < 384) { src = W2;  K = 512; N = 512; realN = 512; off = W2_OFF;  ktiles = 16; b -= 128; }
    else if (b < 448) { src = W3;  K = 512; N = 128; realN = 128; off = W3_OFF;  ktiles = 16; b -= 384; }
    else              { src = Wc1; K = 128; N = 128; realN = 64;  off = WC1_OFF; ktiles = 4;  b -= 448; }
    int kb = (b % ktiles) * 32, nb = (b / ktiles) * 32;
    int tx = threadIdx.x, ty = threadIdx.y;   // 32 x 8
    #pragma unroll
    for (int i = ty; i < 32; i += 8) {
        int k = kb + i, n = nb + tx;
        float v = 0.f;
        if (k < K && n < realN) v = src[(size_t)k * realN + n];
        t[i][tx] = rnatf(v);
    }
    __syncthreads();
    #pragma unroll
    for (int i = ty; i < 32; i += 8) {
        int n = nb + i, k = kb + tx;
        if (n < N && k < K) g_Wr[off + (size_t)n * K + k] = t[tx][i];
    }
}

__global__ void k_round_x(const float* __restrict__ x) {
    int i = blockIdx.x * blockDim.x + threadIdx.x;
    if (i >= N_NODES * FIN / 4) return;
    float4 v = ((const float4*)x)[i];
    ((float4*)g_bufB)[i] = make_float4(rnatf(v.x), rnatf(v.y), rnatf(v.z), rnatf(v.w));
}

// ---------------- tf32 tensor-core GEMM (ldmatrix path) ----------------
#define GBN 128
#define GBK 16
#define SMS 20

__device__ __forceinline__ void mma_tf32(float c[4], uint32_t a0, uint32_t a1,
                                         uint32_t a2, uint32_t a3,
                                         uint32_t b0, uint32_t b1) {
    asm volatile(
        "mma.sync.aligned.m16n8k8.row.col.f32.tf32.tf32.f32 "
        "{%0,%1,%2,%3}, {%4,%5,%6,%7}, {%8,%9}, {%0,%1,%2,%3};"
        : "+f"(c[0]), "+f"(c[1]), "+f"(c[2]), "+f"(c[3])
        : "r"(a0), "r"(a1), "r"(a2), "r"(a3), "r"(b0), "r"(b1));
}

template<int MFRAG>
__global__ __launch_bounds__(256, 2) void k_gemm_tc(int M, int K, int N, int woff,
                                                    const float* __restrict__ as,
                                                    const float* __restrict__ ad) {
    const int BM = MFRAG * 32;
    const float* __restrict__ A  = g_bufB;
    const float* __restrict__ Bt = g_Wr + woff;      // [N][K]
    __half* __restrict__ C = g_bufH;

    __shared__ __align__(16) float As[2][MFRAG * 32][SMS];
    __shared__ __align__(16) float Bs[2][GBN][SMS];
    __shared__ __align__(16) float as_sm[GBN], ad_sm[GBN];
    __shared__ float red_s[MFRAG * 32][4], red_d[MFRAG * 32][4];

    const uint32_t ASTG = BM * SMS * 4;
    const uint32_t BSTG = GBN * SMS * 4;

    int tid  = threadIdx.x;
    int warp = tid >> 5;
    int lane = tid & 31;
    int wm = warp >> 2;
    int wn = warp & 3;
    int sub = lane >> 3, rr = lane & 7;

    int m0 = blockIdx.y * BM;
    int n0 = blockIdx.x * GBN;

    if (as != nullptr && tid < 32) {
        ((float4*)as_sm)[tid] = ((const float4*)(as + blockIdx.x * HD))[tid];
        ((float4*)ad_sm)[tid] = ((const float4*)(ad + blockIdx.x * HD))[tid];
    }

    uint32_t aBase = (uint32_t)__cvta_generic_to_shared(&As[0][0][0]);
    uint32_t bBase = (uint32_t)__cvta_generic_to_shared(&Bs[0][0][0]);
    uint32_t aAddr[MFRAG], bAddr[2];
    #pragma unroll
    for (int mf = 0; mf < MFRAG; mf++)
        aAddr[mf] = aBase + (((wm * (MFRAG * 16) + mf * 16 + (sub & 1) * 8 + rr) * SMS
                              + (sub >> 1) * 4) << 2);
    #pragma unroll
    for (int p = 0; p < 2; p++)
        bAddr[p] = bBase + (((wn * 32 + p * 16 + ((sub >> 1) & 1) * 8 + rr) * SMS
                             + (sub & 1) * 4) << 2);

    float acc[MFRAG][4][4];
    #pragma unroll
    for (int i = 0; i < MFRAG; i++)
        #pragma unroll
        for (int j = 0; j < 4; j++)
            #pragma unroll
            for (int r = 0; r < 4; r++) acc[i][j][r] = 0.f;

    auto load_stage = [&](int s, int k0) {
        for (int i = tid; i < BM * 4; i += 256) {
            int row = i >> 2, c4 = i & 3;
            const float* ga = A + (size_t)(m0 + row) * K + k0 + c4 * 4;
            uint32_t da = (uint32_t)__cvta_generic_to_shared(&As[s][row][c4 * 4]);
            asm volatile("cp.async.cg.shared.global [%0], [%1], 16;" :: "r"(da), "l"(ga));
        }
        for (int i = tid; i < GBN * 4; i += 256) {
            int row = i >> 2, c4 = i & 3;
            const float* gb = Bt + (size_t)(n0 + row) * K + k0 + c4 * 4;
            uint32_t db = (uint32_t)__cvta_generic_to_shared(&Bs[s][row][c4 * 4]);
            asm volatile("cp.async.cg.shared.global [%0], [%1], 16;" :: "r"(db), "l"(gb));
        }
    };

    const int nT = K / GBK;
    load_stage(0, 0);
    asm volatile("cp.async.commit_group;");

    for (int t = 0; t < nT; t++) {
        if (t + 1 < nT) {
            load_stage((t + 1) & 1, (t + 1) * GBK);
            asm volatile("cp.async.commit_group;");
            asm volatile("cp.async.wait_group 1;");
        } else {
            asm volatile("cp.async.wait_group 0;");
        }
        __syncthreads();

        uint32_t aO = (t & 1) * ASTG, bO = (t & 1) * BSTG;
        #pragma unroll
        for (int kc = 0; kc < GBK; kc += 8) {
            uint32_t af[MFRAG][4];
            #pragma unroll
            for (int mf = 0; mf < MFRAG; mf++)
                LDSM4(af[mf][0], af[mf][1], af[mf][2], af[mf][3],
                      aAddr[mf] + aO + kc * 4);
            uint32_t bf[4][2];
            LDSM4(bf[0][0], bf[0][1], bf[1][0], bf[1][1], bAddr[0] + bO + kc * 4);
            LDSM4(bf[2][0], bf[2][1], bf[3][0], bf[3][1], bAddr[1] + bO + kc * 4);
            #pragma unroll
            for (int mf = 0; mf < MFRAG; mf++)
                #pragma unroll
                for (int nf = 0; nf < 4; nf++)
                    mma_tf32(acc[mf][nf], af[mf][0], af[mf][1], af[mf][2], af[mf][3],
                             bf[nf][0], bf[nf][1]);
        }
        __syncthreads();
    }

    int g = lane >> 2, t4 = lane & 3;

    // epilogue 1: store C as fp16
    #pragma unroll
    for (int mf = 0; mf < MFRAG; mf++) {
        int r0 = m0 + wm * (MFRAG * 16) + mf * 16 + g;
        int r1 = r0 + 8;
        #pragma unroll
        for (int nf = 0; nf < 4; nf++) {
            int c = n0 + wn * 32 + nf * 8 + t4 * 2;
            if (r0 < M)
                *(__half2*)(C + (size_t)r0 * N + c) =
                    __floats2half2_rn(acc[mf][nf][0], acc[mf][nf][1]);
            if (r1 < M)
                *(__half2*)(C + (size_t)r1 * N + c) =
                    __floats2half2_rn(acc[mf][nf][2], acc[mf][nf][3]);
        }
    }

    // epilogue 2: fused attention coefficients (fp32 accumulators)
    if (as != nullptr) {
        #pragma unroll
        for (int mf = 0; mf < MFRAG; mf++) {
            float ps0 = 0.f, pd0 = 0.f, ps1 = 0.f, pd1 = 0.f;
            #pragma unroll
            for (int nf = 0; nf < 4; nf++) {
                int c = wn * 32 + nf * 8 + t4 * 2;
                float a0 = as_sm[c], a1 = as_sm[c + 1];
                float d0 = ad_sm[c], d1 = ad_sm[c + 1];
                ps0 += acc[mf][nf][0] * a0 + acc[mf][nf][1] * a1;
                pd0 += acc[mf][nf][0] * d0 + acc[mf][nf][1] * d1;
                ps1 += acc[mf][nf][2] * a0 + acc[mf][nf][3] * a1;
                pd1 += acc[mf][nf][2] * d0 + acc[mf][nf][3] * d1;
            }
            ps0 += __shfl_xor_sync(0xFFFFFFFFu, ps0, 1);
            ps0 += __shfl_xor_sync(0xFFFFFFFFu, ps0, 2);
            pd0 += __shfl_xor_sync(0xFFFFFFFFu, pd0, 1);
            pd0 += __shfl_xor_sync(0xFFFFFFFFu, pd0, 2);
            ps1 += __shfl_xor_sync(0xFFFFFFFFu, ps1, 1);
            ps1 += __shfl_xor_sync(0xFFFFFFFFu, ps1, 2);
            pd1 += __shfl_xor_sync(0xFFFFFFFFu, pd1, 1);
            pd1 += __shfl_xor_sync(0xFFFFFFFFu, pd1, 2);
            if (t4 == 0) {
                int r0 = wm * (MFRAG * 16) + mf * 16 + g;
                red_s[r0][wn] = ps0;  red_d[r0][wn] = pd0;
                red_s[r0 + 8][wn] = ps1;  red_d[r0 + 8][wn] = pd1;
            }
        }
        __syncthreads();
        if (tid < BM) {
            int node = m0 + tid;
            if (node < M) {
                float s = red_s[tid][0] + red_s[tid][1] + red_s[tid][2] + red_s[tid][3];
                float d = red_d[tid][0] + red_d[tid][1] + red_d[tid][2] + red_d[tid][3];
                int H = gridDim.x;
                g_als[node * H + blockIdx.x] = s;
                g_ald[node * H + blockIdx.x] = d;
            }
        }
    }
}

// ---------------- segment-softmax aggregation ----------------
// Two-pass (exact segment max, then exp-sum), 4-edge unrolled for MLP.
// One warp per (node, head). fp16 feature gather (8B/lane).
__global__ void k_aggregate(const float* __restrict__ bias,
                            float* __restrict__ outExt,
                            int H, int applyElu, int outSel) {
    int gw = (blockIdx.x * blockDim.x + threadIdx.x) >> 5;
    int lane = threadIdx.x & 31;
    int node = gw / H, head = gw - node * H;
    if (node >= N_NODES) return;
    int beg = g_rowptr[node], end = g_rowptr[node + 1];
    float ad = g_ald[node * H + head];
    const int F = H * HD;
    const __half* __restrict__ hb = g_bufH + head * HD + lane * 4;
    const float* __restrict__ als = g_als;
    const int* __restrict__ col = g_colsrc;

    // ---- pass 1: segment max (unrolled x4; als is small + L1-hot) ----
    float m = -1e30f;
    int j = beg;
    for (; j + 4 <= end; j += 4) {
        int s0 = col[j], s1 = col[j + 1], s2 = col[j + 2], s3 = col[j + 3];
        float e0 = lrelu(als[s0 * H + head] + ad);
        float e1 = lrelu(als[s1 * H + head] + ad);
        float e2 = lrelu(als[s2 * H + head] + ad);
        float e3 = lrelu(als[s3 * H + head] + ad);
        m = fmaxf(m, fmaxf(fmaxf(e0, e1), fmaxf(e2, e3)));
    }
    for (; j < end; j++)
        m = fmaxf(m, lrelu(als[col[j] * H + head] + ad));

    // ---- pass 2: exp-sum + weighted gather (4 independent loads in flight) ----
    float denom = 0.f;
    float4 acc = make_float4(0.f, 0.f, 0.f, 0.f);
    j = beg;
    for (; j + 4 <= end; j += 4) {
        int s0 = col[j], s1 = col[j + 1], s2 = col[j + 2], s3 = col[j + 3];
        // issue all 4 feature gathers first (independent)
        uint2 h0 = *(const uint2*)(hb + (size_t)s0 * F);
        uint2 h1 = *(const uint2*)(hb + (size_t)s1 * F);
        uint2 h2 = *(const uint2*)(hb + (size_t)s2 * F);
        uint2 h3 = *(const uint2*)(hb + (size_t)s3 * F);
        float p0 = __expf(lrelu(als[s0 * H + head] + ad) - m);
        float p1 = __expf(lrelu(als[s1 * H + head] + ad) - m);
        float p2 = __expf(lrelu(als[s2 * H + head] + ad) - m);
        float p3 = __expf(lrelu(als[s3 * H + head] + ad) - m);
        denom += (p0 + p1) + (p2 + p3);
        float2 a0 = __half22float2(*(const __half2*)&h0.x);
        float2 b0 = __half22float2(*(const __half2*)&h0.y);
        float2 a1 = __half22float2(*(const __half2*)&h1.x);
        float2 b1 = __half22float2(*(const __half2*)&h1.y);
        float2 a2 = __half22float2(*(const __half2*)&h2.x);
        float2 b2 = __half22float2(*(const __half2*)&h2.y);
        float2 a3 = __half22float2(*(const __half2*)&h3.x);
        float2 b3 = __half22float2(*(const __half2*)&h3.y);
        acc.x += p0 * a0.x + p1 * a1.x + p2 * a2.x + p3 * a3.x;
        acc.y += p0 * a0.y + p1 * a1.y + p2 * a2.y + p3 * a3.y;
        acc.z += p0 * b0.x + p1 * b1.x + p2 * b2.x + p3 * b3.x;
        acc.w += p0 * b0.y + p1 * b1.y + p2 * b2.y + p3 * b3.y;
    }
    for (; j < end; j++) {
        int s = col[j];
        uint2 hv = *(const uint2*)(hb + (size_t)s * F);
        float p = __expf(lrelu(als[s * H + head] + ad) - m);
        denom += p;
        float2 f01 = __half22float2(*(const __half2*)&hv.x);
        float2 f23 = __half22float2(*(const __half2*)&hv.y);
        acc.x += p * f01.x; acc.y += p * f01.y;
        acc.z += p * f23.x; acc.w += p * f23.y;
    }

    float inv = 1.f / (denom + 1e-16f);
    float4 b = *(const float4*)(bias + head * HD + lane * 4);
    float o0 = acc.x * inv + b.x;
    float o1 = acc.y * inv + b.y;
    float o2 = acc.z * inv + b.z;
    float o3 = acc.w * inv + b.w;
    if (applyElu) {
        o0 = (o0 > 0.f) ? o0 : expm1f(o0);
        o1 = (o1 > 0.f) ? o1 : expm1f(o1);
        o2 = (o2 > 0.f) ? o2 : expm1f(o2);
        o3 = (o3 > 0.f) ? o3 : expm1f(o3);
    }
    size_t idx = (size_t)node * F + head * HD + lane * 4;
    if (outSel) {
        *(float4*)(outExt + idx) = make_float4(o0, o1, o2, o3);   // emb fp32
        *(float4*)(g_bufB + idx) =
            make_float4(rnatf(o0), rnatf(o1), rnatf(o2), rnatf(o3));  // classifier A
    } else {
        *(float4*)(g_bufB + idx) =
            make_float4(rnatf(o0), rnatf(o1), rnatf(o2), rnatf(o3));
    }
}

// ---------------- classifier finisher: out = relu(hid+bc1) @ Wc2 + bc2 ----------------
__global__ void k_cls2(const float* __restrict__ bc1,
                       const float* __restrict__ Wc2,
                       const float* __restrict__ bc2,
                       float* __restrict__ out) {
    int gw = (blockIdx.x * blockDim.x + threadIdx.x) >> 5;
    int lane = threadIdx.x & 31;
    if (gw >= N_NODES) return;
    float h0 = __half2float(g_bufH[(size_t)gw * 128 + lane]);
    float h1 = __half2float(g_bufH[(size_t)gw * 128 + lane + 32]);
    h0 = fmaxf(h0 + bc1[lane], 0.f);
    h1 = fmaxf(h1 + bc1[lane + 32], 0.f);
    float o0 = h0 * Wc2[lane * 2]     + h1 * Wc2[(lane + 32) * 2];
    float o1 = h0 * Wc2[lane * 2 + 1] + h1 * Wc2[(lane + 32) * 2 + 1];
    #pragma unroll
    for (int o = 16; o; o >>= 1) {
        o0 += __shfl_xor_sync(0xFFFFFFFFu, o0, o);
        o1 += __shfl_xor_sync(0xFFFFFFFFu, o1, o);
    }
    if (lane == 0) {
        out[gw * 2]     = o0 + bc2[0];
        out[gw * 2 + 1] = o1 + bc2[1];
    }
}

// ---------------- launch: kernel launches ONLY ----------------
extern "C" void kernel_launch(void* const* d_in, const int* in_sizes, int n_in,
                              void* d_out, int out_size) {
    const float* x   = (const float*)d_in[0];
    const int*   ei  = (const int*)  d_in[1];
    const float* W1  = (const float*)d_in[2];
    const float* a1s = (const float*)d_in[3];
    const float* a1d = (const float*)d_in[4];
    const float* b1  = (const float*)d_in[5];
    const float* W2  = (const float*)d_in[6];
    const float* a2s = (const float*)d_in[7];
    const float* a2d = (const float*)d_in[8];
    const float* b2  = (const float*)d_in[9];
    const float* W3  = (const float*)d_in[10];
    const float* a3s = (const float*)d_in[11];
    const float* a3d = (const float*)d_in[12];
    const float* b3  = (const float*)d_in[13];
    const float* Wc1 = (const float*)d_in[14];
    const float* bc1 = (const float*)d_in[15];
    const float* Wc2 = (const float*)d_in[16];
    const float* bc2 = (const float*)d_in[17];

    float* out = (float*)d_out;                 // [N,2]
    float* emb = out + (size_t)N_NODES * 2;     // [N,128]

    dim3 gT(256);
    const int blocksH4 = (N_NODES * HH + 7) / 8;
    const int blocksH1 = (N_NODES * 1  + 7) / 8;
    const int gy4 = M_PAD / 128;   // 79
    const int gy2 = M_PAD / 64;    // 158

    // prep (3 launches, keeps L1 GEMM in the ncu-profiled slot)
    k_trans_all<<<464, dim3(32, 8)>>>(W1, W2, W3, Wc1);
    k_round_x<<<(N_NODES * FIN / 4 + 255) / 256, 256>>>(x);
    k_zero_deg<<<(N_NODES + 255) / 256, 256>>>();

    // ---- layer 1 GEMM (+fused attn) ----
    k_gemm_tc<4><<<dim3(F1 / GBN, gy4), gT>>>(N_NODES, FIN, F1, W1_OFF, a1s, a1d);

    // CSR build
    k_count<<<(E_TOT + 255) / 256, 256>>>(ei);
    k_scan <<<1, 1024>>>();
    k_fill <<<(E_TOT + 255) / 256, 256>>>(ei);

    // ---- layer 1 aggregate -> bufB (ELU, tf32) ----
    k_aggregate<<<blocksH4, gT>>>(b1, nullptr, HH, 1, 0);

    // ---- layer 2 ----
    k_gemm_tc<4><<<dim3(F1 / GBN, gy4), gT>>>(N_NODES, F1, F1, W2_OFF, a2s, a2d);
    k_aggregate<<<blocksH4, gT>>>(b2, nullptr, HH, 1, 0);

    // ---- layer 3 (H=1) ----
    k_gemm_tc<2><<<dim3(HD / GBN, gy2), gT>>>(N_NODES, F1, HD, W3_OFF, a3s, a3d);
    k_aggregate<<<blocksH1, gT>>>(b3, emb, 1, 0, 1);

    // ---- classifier ----
    k_gemm_tc<2><<<dim3(1, gy2), gT>>>(N_NODES, HD, 128, WC1_OFF, nullptr, nullptr);
    k_cls2<<<blocksH1, gT>>>(bc1, Wc2, bc2, out);
}

// round 17
// speedup vs baseline: 1.6529x; 1.0466x over previous
#include <cuda_runtime.h>
#include <cuda_fp16.h>
#include <math.h>
#include <stdint.h>

// ---------------- problem constants ----------------
#define N_NODES 10000
#define E_EDGES 320000
#define E_TOT   (E_EDGES + N_NODES)   // with self-loops
#define FIN     256
#define HD      128                   // channels per head
#define HH      4                     // heads (layers 1,2)
#define F1      (HH * HD)             // 512
#define M_PAD   10112                 // 79*128 = 158*64

// weight scratch offsets (floats): TRANSPOSED tf32-rounded copies Wt[N][K]
#define W1_OFF  0                     // 512*256 = 131072
#define W2_OFF  131072                // 512*512 = 262144
#define W3_OFF  393216                // 128*512 = 65536
#define WC1_OFF 458752                // 128*128 = 16384 (rows 64..127 zero)
#define W_TOT   475136

// ---------------- device scratch ----------------
__device__ __align__(16) __half g_bufH[(size_t)N_NODES * F1];  // GEMM C, fp16 (10 MB)
__device__ __align__(16) float g_bufB[(size_t)M_PAD * F1];     // GEMM A (tf32, padded)
__device__ __align__(16) float g_Wr[W_TOT];
__device__ __align__(16) float g_als[N_NODES * HH];
__device__ __align__(16) float g_ald[N_NODES * HH];
__device__ __align__(16) float g_mx[N_NODES * HH];             // per-(dst,head) max of als
__device__ int   g_deg[N_NODES];
__device__ int   g_rowptr[N_NODES + 1];
__device__ int   g_cursor[N_NODES];
__device__ int   g_colsrc[E_TOT];

// ---------------- helpers ----------------
__device__ __forceinline__ float rnatf(float x) {
    uint32_t u;
    asm("cvt.rna.tf32.f32 %0, %1;" : "=r"(u) : "f"(x));
    return __uint_as_float(u);
}

__device__ __forceinline__ float lrelu(float e) { return (e > 0.f) ? e : 0.2f * e; }

// float atomic max (sign-aware int/uint trick); init must be very negative
__device__ __forceinline__ void atomicMaxFloat(float* addr, float value) {
    if (value >= 0.f)
        atomicMax((int*)addr, __float_as_int(value));
    else
        atomicMin((unsigned int*)addr, __float_as_uint(value));
}

#define LDSM4(R0, R1, R2, R3, ADDR) \
    asm volatile("ldmatrix.sync.aligned.m8n8.x4.shared.b16 {%0,%1,%2,%3}, [%4];" \
        : "=r"(R0), "=r"(R1), "=r"(R2), "=r"(R3) : "r"(ADDR))

// ---------------- CSR build (dst-indexed) ----------------
__global__ void k_zero_deg() {
    int i = blockIdx.x * blockDim.x + threadIdx.x;
    if (i < N_NODES) g_deg[i] = 0;
}

__global__ void k_count(const int* __restrict__ ei) {
    int i = blockIdx.x * blockDim.x + threadIdx.x;
    if (i < E_TOT) {
        int d = (i < E_EDGES) ? ei[E_EDGES + i] : (i - E_EDGES);
        if ((unsigned)d < (unsigned)N_NODES)
            atomicAdd(&g_deg[d], 1);
    }
}

__global__ void k_scan() {
    __shared__ int wsum[32];
    const int T = 1024;
    const int CH = (N_NODES + T - 1) / T;
    int tid = threadIdx.x;
    int start = tid * CH;
    int local = 0;
    for (int i = 0; i < CH; i++) {
        int idx = start + i;
        if (idx < N_NODES) local += g_deg[idx];
    }
    int lane = tid & 31, warp = tid >> 5;
    int v = local;
    #pragma unroll
    for (int o = 1; o < 32; o <<= 1) {
        int t = __shfl_up_sync(0xFFFFFFFFu, v, o);
        if (lane >= o) v += t;
    }
    if (lane == 31) wsum[warp] = v;
    __syncthreads();
    if (warp == 0) {
        int w = wsum[lane];
        #pragma unroll
        for (int o = 1; o < 32; o <<= 1) {
            int t = __shfl_up_sync(0xFFFFFFFFu, w, o);
            if (lane >= o) w += t;
        }
        wsum[lane] = w;
    }
    __syncthreads();
    int incl = v + (warp > 0 ? wsum[warp - 1] : 0);
    int run = incl - local;
    for (int i = 0; i < CH; i++) {
        int idx = start + i;
        if (idx < N_NODES) {
            g_rowptr[idx] = run;
            g_cursor[idx] = run;
            run += g_deg[idx];
        }
    }
    if (tid == T - 1) g_rowptr[N_NODES] = run;
}

__global__ void k_fill(const int* __restrict__ ei) {
    int i = blockIdx.x * blockDim.x + threadIdx.x;
    if (i < E_TOT) {
        int s, d;
        if (i < E_EDGES) { s = ei[i]; d = ei[E_EDGES + i]; }
        else             { s = i - E_EDGES; d = s; }
        if ((unsigned)d >= (unsigned)N_NODES) return;
        if ((unsigned)s >= (unsigned)N_NODES) s = 0;
        int pos = atomicAdd(&g_cursor[d], 1);
        if (pos < E_TOT) g_colsrc[pos] = s;
    }
}

// ---------------- edge-parallel segment max of als into g_mx ----------------
// g_mx initialized to -1e30 by the preceding GEMM's epilogue.
__global__ void k_edge_max(const int* __restrict__ ei, int H) {
    int i = blockIdx.x * blockDim.x + threadIdx.x;
    if (i >= E_TOT) return;
    int s, d;
    if (i < E_EDGES) { s = ei[i]; d = ei[E_EDGES + i]; }
    else             { s = i - E_EDGES; d = s; }
    if ((unsigned)d >= (unsigned)N_NODES) return;
    if ((unsigned)s >= (unsigned)N_NODES) s = 0;
    if (H == HH) {
        float4 v = *(const float4*)(g_als + s * HH);
        atomicMaxFloat(&g_mx[d * HH + 0], v.x);
        atomicMaxFloat(&g_mx[d * HH + 1], v.y);
        atomicMaxFloat(&g_mx[d * HH + 2], v.z);
        atomicMaxFloat(&g_mx[d * HH + 3], v.w);
    } else {
        atomicMaxFloat(&g_mx[d], g_als[s]);
    }
}

// ---------------- weight transpose + tf32 round: g_Wr holds Wt[N][K] ----------------
__global__ void k_trans_all(const float* __restrict__ W1,
                            const float* __restrict__ W2,
                            const float* __restrict__ W3,
                            const float* __restrict__ Wc1) {
    __shared__ float t[32][33];
    int b = blockIdx.x;
    const float* src; int K, N, realN, off, ktiles;
    if (b < 128)      { src = W1;  K = 256; N = 512; realN = 512; off = W1_OFF;  ktiles = 8;  }
    else if (b < 384) { src = W2;  K = 512; N = 512; realN = 512; off = W2_OFF;  ktiles = 16; b -= 128; }
    else if (b < 448) { src = W3;  K = 512; N = 128; realN = 128; off = W3_OFF;  ktiles = 16; b -= 384; }
    else              { src = Wc1; K = 128; N = 128; realN = 64;  off = WC1_OFF; ktiles = 4;  b -= 448; }
    int kb = (b % ktiles) * 32, nb = (b / ktiles) * 32;
    int tx = threadIdx.x, ty = threadIdx.y;   // 32 x 8
    #pragma unroll
    for (int i = ty; i < 32; i += 8) {
        int k = kb + i, n = nb + tx;
        float v = 0.f;
        if (k < K && n < realN) v = src[(size_t)k * realN + n];
        t[i][tx] = rnatf(v);
    }
    __syncthreads();
    #pragma unroll
    for (int i = ty; i < 32; i += 8) {
        int n = nb + i, k = kb + tx;
        if (n < N && k < K) g_Wr[off + (size_t)n * K + k] = t[tx][i];
    }
}

__global__ void k_round_x(const float* __restrict__ x) {
    int i = blockIdx.x * blockDim.x + threadIdx.x;
    if (i >= N_NODES * FIN / 4) return;
    float4 v = ((const float4*)x)[i];
    ((float4*)g_bufB)[i] = make_float4(rnatf(v.x), rnatf(v.y), rnatf(v.z), rnatf(v.w));
}

// ---------------- tf32 tensor-core GEMM (ldmatrix path) ----------------
#define GBN 128
#define GBK 16
#define SMS 20

__device__ __forceinline__ void mma_tf32(float c[4], uint32_t a0, uint32_t a1,
                                         uint32_t a2, uint32_t a3,
                                         uint32_t b0, uint32_t b1) {
    asm volatile(
        "mma.sync.aligned.m16n8k8.row.col.f32.tf32.tf32.f32 "
        "{%0,%1,%2,%3}, {%4,%5,%6,%7}, {%8,%9}, {%0,%1,%2,%3};"
        : "+f"(c[0]), "+f"(c[1]), "+f"(c[2]), "+f"(c[3])
        : "r"(a0), "r"(a1), "r"(a2), "r"(a3), "r"(b0), "r"(b1));
}

template<int MFRAG>
__global__ __launch_bounds__(256, 2) void k_gemm_tc(int M, int K, int N, int woff,
                                                    const float* __restrict__ as,
                                                    const float* __restrict__ ad) {
    const int BM = MFRAG * 32;
    const float* __restrict__ A  = g_bufB;
    const float* __restrict__ Bt = g_Wr + woff;      // [N][K]
    __half* __restrict__ C = g_bufH;

    __shared__ __align__(16) float As[2][MFRAG * 32][SMS];
    __shared__ __align__(16) float Bs[2][GBN][SMS];
    __shared__ __align__(16) float as_sm[GBN], ad_sm[GBN];
    __shared__ float red_s[MFRAG * 32][4], red_d[MFRAG * 32][4];

    const uint32_t ASTG = BM * SMS * 4;
    const uint32_t BSTG = GBN * SMS * 4;

    int tid  = threadIdx.x;
    int warp = tid >> 5;
    int lane = tid & 31;
    int wm = warp >> 2;
    int wn = warp & 3;
    int sub = lane >> 3, rr = lane & 7;

    int m0 = blockIdx.y * BM;
    int n0 = blockIdx.x * GBN;

    if (as != nullptr && tid < 32) {
        ((float4*)as_sm)[tid] = ((const float4*)(as + blockIdx.x * HD))[tid];
        ((float4*)ad_sm)[tid] = ((const float4*)(ad + blockIdx.x * HD))[tid];
    }

    uint32_t aBase = (uint32_t)__cvta_generic_to_shared(&As[0][0][0]);
    uint32_t bBase = (uint32_t)__cvta_generic_to_shared(&Bs[0][0][0]);
    uint32_t aAddr[MFRAG], bAddr[2];
    #pragma unroll
    for (int mf = 0; mf < MFRAG; mf++)
        aAddr[mf] = aBase + (((wm * (MFRAG * 16) + mf * 16 + (sub & 1) * 8 + rr) * SMS
                              + (sub >> 1) * 4) << 2);
    #pragma unroll
    for (int p = 0; p < 2; p++)
        bAddr[p] = bBase + (((wn * 32 + p * 16 + ((sub >> 1) & 1) * 8 + rr) * SMS
                             + (sub & 1) * 4) << 2);

    float acc[MFRAG][4][4];
    #pragma unroll
    for (int i = 0; i < MFRAG; i++)
        #pragma unroll
        for (int j = 0; j < 4; j++)
            #pragma unroll
            for (int r = 0; r < 4; r++) acc[i][j][r] = 0.f;

    auto load_stage = [&](int s, int k0) {
        for (int i = tid; i < BM * 4; i += 256) {
            int row = i >> 2, c4 = i & 3;
            const float* ga = A + (size_t)(m0 + row) * K + k0 + c4 * 4;
            uint32_t da = (uint32_t)__cvta_generic_to_shared(&As[s][row][c4 * 4]);
            asm volatile("cp.async.cg.shared.global [%0], [%1], 16;" :: "r"(da), "l"(ga));
        }
        for (int i = tid; i < GBN * 4; i += 256) {
            int row = i >> 2, c4 = i & 3;
            const float* gb = Bt + (size_t)(n0 + row) * K + k0 + c4 * 4;
            uint32_t db = (uint32_t)__cvta_generic_to_shared(&Bs[s][row][c4 * 4]);
            asm volatile("cp.async.cg.shared.global [%0], [%1], 16;" :: "r"(db), "l"(gb));
        }
    };

    const int nT = K / GBK;
    load_stage(0, 0);
    asm volatile("cp.async.commit_group;");

    for (int t = 0; t < nT; t++) {
        if (t + 1 < nT) {
            load_stage((t + 1) & 1, (t + 1) * GBK);
            asm volatile("cp.async.commit_group;");
            asm volatile("cp.async.wait_group 1;");
        } else {
            asm volatile("cp.async.wait_group 0;");
        }
        __syncthreads();

        uint32_t aO = (t & 1) * ASTG, bO = (t & 1) * BSTG;
        #pragma unroll
        for (int kc = 0; kc < GBK; kc += 8) {
            uint32_t af[MFRAG][4];
            #pragma unroll
            for (int mf = 0; mf < MFRAG; mf++)
                LDSM4(af[mf][0], af[mf][1], af[mf][2], af[mf][3],
                      aAddr[mf] + aO + kc * 4);
            uint32_t bf[4][2];
            LDSM4(bf[0][0], bf[0][1], bf[1][0], bf[1][1], bAddr[0] + bO + kc * 4);
            LDSM4(bf[2][0], bf[2][1], bf[3][0], bf[3][1], bAddr[1] + bO + kc * 4);
            #pragma unroll
            for (int mf = 0; mf < MFRAG; mf++)
                #pragma unroll
                for (int nf = 0; nf < 4; nf++)
                    mma_tf32(acc[mf][nf], af[mf][0], af[mf][1], af[mf][2], af[mf][3],
                             bf[nf][0], bf[nf][1]);
        }
        __syncthreads();
    }

    int g = lane >> 2, t4 = lane & 3;

    // epilogue 1: store C as fp16
    #pragma unroll
    for (int mf = 0; mf < MFRAG; mf++) {
        int r0 = m0 + wm * (MFRAG * 16) + mf * 16 + g;
        int r1 = r0 + 8;
        #pragma unroll
        for (int nf = 0; nf < 4; nf++) {
            int c = n0 + wn * 32 + nf * 8 + t4 * 2;
            if (r0 < M)
                *(__half2*)(C + (size_t)r0 * N + c) =
                    __floats2half2_rn(acc[mf][nf][0], acc[mf][nf][1]);
            if (r1 < M)
                *(__half2*)(C + (size_t)r1 * N + c) =
                    __floats2half2_rn(acc[mf][nf][2], acc[mf][nf][3]);
        }
    }

    // epilogue 2: fused attention coefficients (fp32 accumulators) + g_mx init
    if (as != nullptr) {
        #pragma unroll
        for (int mf = 0; mf < MFRAG; mf++) {
            float ps0 = 0.f, pd0 = 0.f, ps1 = 0.f, pd1 = 0.f;
            #pragma unroll
            for (int nf = 0; nf < 4; nf++) {
                int c = wn * 32 + nf * 8 + t4 * 2;
                float a0 = as_sm[c], a1 = as_sm[c + 1];
                float d0 = ad_sm[c], d1 = ad_sm[c + 1];
                ps0 += acc[mf][nf][0] * a0 + acc[mf][nf][1] * a1;
                pd0 += acc[mf][nf][0] * d0 + acc[mf][nf][1] * d1;
                ps1 += acc[mf][nf][2] * a0 + acc[mf][nf][3] * a1;
                pd1 += acc[mf][nf][2] * d0 + acc[mf][nf][3] * d1;
            }
            ps0 += __shfl_xor_sync(0xFFFFFFFFu, ps0, 1);
            ps0 += __shfl_xor_sync(0xFFFFFFFFu, ps0, 2);
            pd0 += __shfl_xor_sync(0xFFFFFFFFu, pd0, 1);
            pd0 += __shfl_xor_sync(0xFFFFFFFFu, pd0, 2);
            ps1 += __shfl_xor_sync(0xFFFFFFFFu, ps1, 1);
            ps1 += __shfl_xor_sync(0xFFFFFFFFu, ps1, 2);
            pd1 += __shfl_xor_sync(0xFFFFFFFFu, pd1, 1);
            pd1 += __shfl_xor_sync(0xFFFFFFFFu, pd1, 2);
            if (t4 == 0) {
                int r0 = wm * (MFRAG * 16) + mf * 16 + g;
                red_s[r0][wn] = ps0;  red_d[r0][wn] = pd0;
                red_s[r0 + 8][wn] = ps1;  red_d[r0 + 8][wn] = pd1;
            }
        }
        __syncthreads();
        if (tid < BM) {
            int node = m0 + tid;
            if (node < M) {
                float s = red_s[tid][0] + red_s[tid][1] + red_s[tid][2] + red_s[tid][3];
                float d = red_d[tid][0] + red_d[tid][1] + red_d[tid][2] + red_d[tid][3];
                int H = gridDim.x;
                g_als[node * H + blockIdx.x] = s;
                g_ald[node * H + blockIdx.x] = d;
                g_mx [node * H + blockIdx.x] = -1e30f;   // init for k_edge_max
            }
        }
    }
}

// ---------------- segment-softmax aggregation (single pass; max from g_mx) ----------------
// One warp per (node, head). fp16 feature gather (8B/lane), 8-edge unrolled.
__global__ void k_aggregate(const float* __restrict__ bias,
                            float* __restrict__ outExt,
                            int H, int applyElu, int outSel) {
    int gw = (blockIdx.x * blockDim.x + threadIdx.x) >> 5;
    int lane = threadIdx.x & 31;
    int node = gw / H, head = gw - node * H;
    if (node >= N_NODES) return;
    int beg = g_rowptr[node], end = g_rowptr[node + 1];
    float ad = g_ald[node * H + head];
    float m = lrelu(g_mx[node * H + head] + ad);   // exact segment max (monotonicity)
    const int F = H * HD;
    const __half* __restrict__ hb = g_bufH + head * HD + lane * 4;
    const float* __restrict__ als = g_als;
    const int* __restrict__ col = g_colsrc;

    float denom = 0.f;
    float4 acc = make_float4(0.f, 0.f, 0.f, 0.f);
    int j = beg;
    for (; j + 8 <= end; j += 8) {
        int s0 = col[j],     s1 = col[j + 1], s2 = col[j + 2], s3 = col[j + 3];
        int s4 = col[j + 4], s5 = col[j + 5], s6 = col[j + 6], s7 = col[j + 7];
        uint2 h0 = *(const uint2*)(hb + (size_t)s0 * F);
        uint2 h1 = *(const uint2*)(hb + (size_t)s1 * F);
        uint2 h2 = *(const uint2*)(hb + (size_t)s2 * F);
        uint2 h3 = *(const uint2*)(hb + (size_t)s3 * F);
        uint2 h4 = *(const uint2*)(hb + (size_t)s4 * F);
        uint2 h5 = *(const uint2*)(hb + (size_t)s5 * F);
        uint2 h6 = *(const uint2*)(hb + (size_t)s6 * F);
        uint2 h7 = *(const uint2*)(hb + (size_t)s7 * F);
        float p0 = __expf(lrelu(als[s0 * H + head] + ad) - m);
        float p1 = __expf(lrelu(als[s1 * H + head] + ad) - m);
        float p2 = __expf(lrelu(als[s2 * H + head] + ad) - m);
        float p3 = __expf(lrelu(als[s3 * H + head] + ad) - m);
        float p4 = __expf(lrelu(als[s4 * H + head] + ad) - m);
        float p5 = __expf(lrelu(als[s5 * H + head] + ad) - m);
        float p6 = __expf(lrelu(als[s6 * H + head] + ad) - m);
        float p7 = __expf(lrelu(als[s7 * H + head] + ad) - m);
        denom += ((p0 + p1) + (p2 + p3)) + ((p4 + p5) + (p6 + p7));
        float2 a0 = __half22float2(*(const __half2*)&h0.x);
        float2 b0 = __half22float2(*(const __half2*)&h0.y);
        float2 a1 = __half22float2(*(const __half2*)&h1.x);
        float2 b1 = __half22float2(*(const __half2*)&h1.y);
        float2 a2 = __half22float2(*(const __half2*)&h2.x);
        float2 b2 = __half22float2(*(const __half2*)&h2.y);
        float2 a3 = __half22float2(*(const __half2*)&h3.x);
        float2 b3 = __half22float2(*(const __half2*)&h3.y);
        float2 a4 = __half22float2(*(const __half2*)&h4.x);
        float2 b4 = __half22float2(*(const __half2*)&h4.y);
        float2 a5 = __half22float2(*(const __half2*)&h5.x);
        float2 b5 = __half22float2(*(const __half2*)&h5.y);
        float2 a6 = __half22float2(*(const __half2*)&h6.x);
        float2 b6 = __half22float2(*(const __half2*)&h6.y);
        float2 a7 = __half22float2(*(const __half2*)&h7.x);
        float2 b7 = __half22float2(*(const __half2*)&h7.y);
        acc.x += (p0 * a0.x + p1 * a1.x + p2 * a2.x + p3 * a3.x)
               + (p4 * a4.x + p5 * a5.x + p6 * a6.x + p7 * a7.x);
        acc.y += (p0 * a0.y + p1 * a1.y + p2 * a2.y + p3 * a3.y)
               + (p4 * a4.y + p5 * a5.y + p6 * a6.y + p7 * a7.y);
        acc.z += (p0 * b0.x + p1 * b1.x + p2 * b2.x + p3 * b3.x)
               + (p4 * b4.x + p5 * b5.x + p6 * b6.x + p7 * b7.x);
        acc.w += (p0 * b0.y + p1 * b1.y + p2 * b2.y + p3 * b3.y)
               + (p4 * b4.y + p5 * b5.y + p6 * b6.y + p7 * b7.y);
    }
    for (; j < end; j++) {
        int s = col[j];
        uint2 hv = *(const uint2*)(hb + (size_t)s * F);
        float p = __expf(lrelu(als[s * H + head] + ad) - m);
        denom += p;
        float2 f01 = __half22float2(*(const __half2*)&hv.x);
        float2 f23 = __half22float2(*(const __half2*)&hv.y);
        acc.x += p * f01.x; acc.y += p * f01.y;
        acc.z += p * f23.x; acc.w += p * f23.y;
    }

    float inv = 1.f / (denom + 1e-16f);
    float4 b = *(const float4*)(bias + head * HD + lane * 4);
    float o0 = acc.x * inv + b.x;
    float o1 = acc.y * inv + b.y;
    float o2 = acc.z * inv + b.z;
    float o3 = acc.w * inv + b.w;
    if (applyElu) {
        o0 = (o0 > 0.f) ? o0 : expm1f(o0);
        o1 = (o1 > 0.f) ? o1 : expm1f(o1);
        o2 = (o2 > 0.f) ? o2 : expm1f(o2);
        o3 = (o3 > 0.f) ? o3 : expm1f(o3);
    }
    size_t idx = (size_t)node * F + head * HD + lane * 4;
    if (outSel) {
        *(float4*)(outExt + idx) = make_float4(o0, o1, o2, o3);   // emb fp32
        *(float4*)(g_bufB + idx) =
            make_float4(rnatf(o0), rnatf(o1), rnatf(o2), rnatf(o3));  // classifier A
    } else {
        *(float4*)(g_bufB + idx) =
            make_float4(rnatf(o0), rnatf(o1), rnatf(o2), rnatf(o3));
    }
}

// ---------------- classifier finisher: out = relu(hid+bc1) @ Wc2 + bc2 ----------------
__global__ void k_cls2(const float* __restrict__ bc1,
                       const float* __restrict__ Wc2,
                       const float* __restrict__ bc2,
                       float* __restrict__ out) {
    int gw = (blockIdx.x * blockDim.x + threadIdx.x) >> 5;
    int lane = threadIdx.x & 31;
    if (gw >= N_NODES) return;
    float h0 = __half2float(g_bufH[(size_t)gw * 128 + lane]);
    float h1 = __half2float(g_bufH[(size_t)gw * 128 + lane + 32]);
    h0 = fmaxf(h0 + bc1[lane], 0.f);
    h1 = fmaxf(h1 + bc1[lane + 32], 0.f);
    float o0 = h0 * Wc2[lane * 2]     + h1 * Wc2[(lane + 32) * 2];
    float o1 = h0 * Wc2[lane * 2 + 1] + h1 * Wc2[(lane + 32) * 2 + 1];
    #pragma unroll
    for (int o = 16; o; o >>= 1) {
        o0 += __shfl_xor_sync(0xFFFFFFFFu, o0, o);
        o1 += __shfl_xor_sync(0xFFFFFFFFu, o1, o);
    }
    if (lane == 0) {
        out[gw * 2]     = o0 + bc2[0];
        out[gw * 2 + 1] = o1 + bc2[1];
    }
}

// ---------------- launch: kernel launches ONLY ----------------
extern "C" void kernel_launch(void* const* d_in, const int* in_sizes, int n_in,
                              void* d_out, int out_size) {
    const float* x   = (const float*)d_in[0];
    const int*   ei  = (const int*)  d_in[1];
    const float* W1  = (const float*)d_in[2];
    const float* a1s = (const float*)d_in[3];
    const float* a1d = (const float*)d_in[4];
    const float* b1  = (const float*)d_in[5];
    const float* W2  = (const float*)d_in[6];
    const float* a2s = (const float*)d_in[7];
    const float* a2d = (const float*)d_in[8];
    const float* b2  = (const float*)d_in[9];
    const float* W3  = (const float*)d_in[10];
    const float* a3s = (const float*)d_in[11];
    const float* a3d = (const float*)d_in[12];
    const float* b3  = (const float*)d_in[13];
    const float* Wc1 = (const float*)d_in[14];
    const float* bc1 = (const float*)d_in[15];
    const float* Wc2 = (const float*)d_in[16];
    const float* bc2 = (const float*)d_in[17];

    float* out = (float*)d_out;                 // [N,2]
    float* emb = out + (size_t)N_NODES * 2;     // [N,128]

    dim3 gT(256);
    const int blocksH4 = (N_NODES * HH + 7) / 8;
    const int blocksH1 = (N_NODES * 1  + 7) / 8;
    const int gy4 = M_PAD / 128;   // 79
    const int gy2 = M_PAD / 64;    // 158
    const int eBlocks = (E_TOT + 255) / 256;

    // prep (3 launches, keeps L1 GEMM in the ncu-profiled slot)
    k_trans_all<<<464, dim3(32, 8)>>>(W1, W2, W3, Wc1);
    k_round_x<<<(N_NODES * FIN / 4 + 255) / 256, 256>>>(x);
    k_zero_deg<<<(N_NODES + 255) / 256, 256>>>();

    // ---- layer 1 GEMM (+fused attn, inits g_mx) ----
    k_gemm_tc<4><<<dim3(F1 / GBN, gy4), gT>>>(N_NODES, FIN, F1, W1_OFF, a1s, a1d);

    // CSR build + edge max (both depend only on ei / L1 attn)
    k_count<<<eBlocks, 256>>>(ei);
    k_scan <<<1, 1024>>>();
    k_fill <<<eBlocks, 256>>>(ei);
    k_edge_max<<<eBlocks, 256>>>(ei, HH);

    // ---- layer 1 aggregate -> bufB (ELU, tf32) ----
    k_aggregate<<<blocksH4, gT>>>(b1, nullptr, HH, 1, 0);

    // ---- layer 2 ----
    k_gemm_tc<4><<<dim3(F1 / GBN, gy4), gT>>>(N_NODES, F1, F1, W2_OFF, a2s, a2d);
    k_edge_max<<<eBlocks, 256>>>(ei, HH);
    k_aggregate<<<blocksH4, gT>>>(b2, nullptr, HH, 1, 0);

    // ---- layer 3 (H=1) ----
    k_gemm_tc<2><<<dim3(HD / GBN, gy2), gT>>>(N_NODES, F1, HD, W3_OFF, a3s, a3d);
    k_edge_max<<<eBlocks, 256>>>(ei, 1);
    k_aggregate<<<blocksH1, gT>>>(b3, emb, 1, 0, 1);

    // ---- classifier ----
    k_gemm_tc<2><<<dim3(1, gy2), gT>>>(N_NODES, HD, 128, WC1_OFF, nullptr, nullptr);
    k_cls2<<<blocksH1, gT>>>(bc1, Wc2, bc2, out);
}